// round 1
// baseline (speedup 1.0000x reference)
#include <cuda_runtime.h>

// ---------------------------------------------------------------------------
// SSRupsampling: x[4,2048,48,48] ->
//   1x1(w_channel) -> 1x1(w_w) -> pixelshuffle-H -> (3x3 conv+ReLU)x2 on 3-col
//   chunks -> 1x1(w_H) -> pixelshuffle-W -> (3x3 conv+ReLU)x2 on 3-row chunks
// Output [4,512,96,96] fp32.
// All fp32 FFMA this round (accuracy-safe baseline).
// ---------------------------------------------------------------------------

// Scratch buffers (static device globals: allocation-free).
__device__ float g_y1[4 * 512 * 2304];        // after w_channel   (18.9 MB)
__device__ float g_y2[4 * 1024 * 2304];       // after w_w         (37.7 MB)
__device__ float g_xp[4 * 512 * 96 * 48];     // after H-shuffle   (37.7 MB)
__device__ float g_t1[4 * 512 * 96 * 48];     // convLR pass 1
__device__ float g_t2[4 * 512 * 96 * 48];     // convLR pass 2
__device__ float g_y3[4 * 1024 * 96 * 48];    // after w_H         (75.5 MB)
__device__ float g_xh[4 * 512 * 96 * 96];     // after W-shuffle   (75.5 MB)
__device__ float g_t3[4 * 512 * 96 * 96];     // convDU pass 1

// ---------------------------------------------------------------------------
// Batched GEMM: C[z] = A @ B[z].  A: [M,K] row-major (shared across batch),
// B[z]: [K,N] row-major, C[z]: [M,N] row-major.
// Tile 128x128, BK=8, 256 threads, 8x8 per-thread register tile.
// Requires M%128==0, N%128==0, K%8==0 (true for all three call sites).
// ---------------------------------------------------------------------------
__global__ __launch_bounds__(256)
void gemm128(const float* __restrict__ A, const float* __restrict__ B,
             float* __restrict__ C, int M, int N, int K,
             long strideB, long strideC) {
    __shared__ float sA[8][128];   // sA[k][m]
    __shared__ float sB[8][128];   // sB[k][n]

    const int tid = threadIdx.x;
    const int n0 = blockIdx.x * 128;
    const int m0 = blockIdx.y * 128;
    const float* Bb = B + (long)blockIdx.z * strideB;
    float* Cb = C + (long)blockIdx.z * strideC;

    const int tx = tid & 15;          // 16 n-groups of 8
    const int ty = tid >> 4;          // 16 m-groups of 8

    // A loader: row = tid/2 (0..127), kvec = (tid&1)*4
    const int arow = tid >> 1;
    const int akv  = (tid & 1) * 4;
    // B loader: krow = tid/32 (0..7), nvec = (tid&31)*4
    const int brow = tid >> 5;
    const int bnv  = (tid & 31) * 4;

    float acc[8][8];
    #pragma unroll
    for (int i = 0; i < 8; i++)
        #pragma unroll
        for (int j = 0; j < 8; j++) acc[i][j] = 0.f;

    for (int k0 = 0; k0 < K; k0 += 8) {
        float4 av = *(const float4*)&A[(long)(m0 + arow) * K + k0 + akv];
        sA[akv + 0][arow] = av.x;
        sA[akv + 1][arow] = av.y;
        sA[akv + 2][arow] = av.z;
        sA[akv + 3][arow] = av.w;
        *(float4*)&sB[brow][bnv] =
            *(const float4*)&Bb[(long)(k0 + brow) * N + n0 + bnv];
        __syncthreads();

        #pragma unroll
        for (int kk = 0; kk < 8; kk++) {
            float a[8], b[8];
            *(float4*)&a[0] = *(const float4*)&sA[kk][ty * 8];
            *(float4*)&a[4] = *(const float4*)&sA[kk][ty * 8 + 4];
            *(float4*)&b[0] = *(const float4*)&sB[kk][tx * 8];
            *(float4*)&b[4] = *(const float4*)&sB[kk][tx * 8 + 4];
            #pragma unroll
            for (int i = 0; i < 8; i++)
                #pragma unroll
                for (int j = 0; j < 8; j++)
                    acc[i][j] += a[i] * b[j];
        }
        __syncthreads();
    }

    #pragma unroll
    for (int i = 0; i < 8; i++) {
        float* crow = &Cb[(long)(m0 + ty * 8 + i) * N + n0 + tx * 8];
        *(float4*)&crow[0] = make_float4(acc[i][0], acc[i][1], acc[i][2], acc[i][3]);
        *(float4*)&crow[4] = make_float4(acc[i][4], acc[i][5], acc[i][6], acc[i][7]);
    }
}

// ---------------------------------------------------------------------------
// Pixel shuffles (cheap permutes).
// ---------------------------------------------------------------------------
__global__ void shuffleH_kernel(const float* __restrict__ src,
                                float* __restrict__ dst, int total) {
    int i = blockIdx.x * blockDim.x + threadIdx.x;
    if (i >= total) return;
    int w  = i % 48;
    int h2 = (i / 48) % 96;
    int c  = (i / (48 * 96)) % 512;
    int n  = i / (48 * 96 * 512);
    // xp[n,c,h2,w] = y2[n, c + 512*(h2&1), h2>>1, w]
    dst[i] = src[(((long)n * 1024 + c + 512 * (h2 & 1)) * 48 + (h2 >> 1)) * 48 + w];
}

__global__ void shuffleW_kernel(const float* __restrict__ src,
                                float* __restrict__ dst, int total) {
    int i = blockIdx.x * blockDim.x + threadIdx.x;
    if (i >= total) return;
    int w2 = i % 96;
    int h  = (i / 96) % 96;
    int c  = (i / (96 * 96)) % 512;
    int n  = i / (96 * 96 * 512);
    // xh[n,c,h,w2] = y3[n, c + 512*(w2&1), h, w2>>1]
    dst[i] = src[(((long)n * 1024 + c + 512 * (w2 & 1)) * 96 + h) * 48 + (w2 >> 1)];
}

// ---------------------------------------------------------------------------
// Generic chunked 3x3 conv + bias + ReLU, implicit GEMM.
// Logical image per (n, chunk): [C=512][L=96][S=3] with zero padding on L and S.
// Element (n, c, l, s) at: n*nStride + c*cStride + l*lStride + (chunk*3+s)*sStride
// Weight tap (dl, ds): w[co*4608 + ci*9 + dl*tapL + ds*tapS]
//   convLR: long=H (kh), short=W (kw) -> tapL=3, tapS=1, sInner=1 (s is stride-1)
//   convDU: long=W (kw), short=H (kh) -> tapL=1, tapS=3, sInner=0 (l is stride-1)
// Block: 64 couts x (32 L-rows x 3 S) = 64x96 outputs, 256 threads,
// each thread: 4 couts x 2 rows x 3 cols = 24 accumulators. BK = 16.
// ---------------------------------------------------------------------------
__global__ __launch_bounds__(256, 2)
void conv3x3_chunk(const float* __restrict__ in, const float* __restrict__ w,
                   const float* __restrict__ bias, float* __restrict__ out,
                   int nChunks, int cStride, int lStride, int sStride,
                   int nStride, int tapL, int tapS, int sInner) {
    // sW[k][tap][co], padded co-stride 65 for conflict-free stores/loads
    __shared__ float sW[16 * 9 * 65];       // 37,440 B
    __shared__ float sI[16 * 34 * 5];       // 10,880 B  (l halo 34, s padded 5)

    const int tid = threadIdx.x;
    const int co0 = blockIdx.x * 64;
    const int l0  = blockIdx.y * 32;
    const int z   = blockIdx.z;
    const int n     = z / nChunks;
    const int chunk = z % nChunks;
    const long base = (long)n * nStride + (long)chunk * 3 * sStride;

    const int tx = tid & 15;         // 16 L-groups of 2 rows
    const int ty = tid >> 4;         // 16 cout-groups of 4
    const int lp = tx * 2;
    const int ty4 = ty * 4;

    float acc[4][2][3];
    #pragma unroll
    for (int m = 0; m < 4; m++)
        #pragma unroll
        for (int li = 0; li < 2; li++)
            #pragma unroll
            for (int s = 0; s < 3; s++) acc[m][li][s] = 0.f;

    for (int ci0 = 0; ci0 < 512; ci0 += 16) {
        // ---- load weights: 16 ci x 9 taps x 64 co = 9216 values ----
        #pragma unroll
        for (int it = 0; it < 36; it++) {
            int i = tid + it * 256;
            int co  = i / 144;
            int rem = i % 144;          // rem = k*9 + t (consecutive per thread)
            int k = rem / 9;
            int t = rem % 9;
            int dl = t / 3, ds = t % 3;
            sW[rem * 65 + co] =
                w[(long)(co0 + co) * 4608 + (ci0 + k) * 9 + dl * tapL + ds * tapS];
        }
        // ---- load input tile: 16 ci x 34 l x 5 s (zero halo) = 2720 ----
        #pragma unroll
        for (int it = 0; it < 11; it++) {
            int j = tid + it * 256;
            if (j < 2720) {
                int k = j / 170;
                int r = j % 170;
                int l, s;
                if (sInner) { l = r / 5; s = r % 5; }      // LR: s is gmem-contig
                else        { s = r / 34; l = r % 34; }    // DU: l is gmem-contig
                int lr = l0 - 1 + l;
                int sr = s - 1;
                float v = 0.f;
                if (lr >= 0 && lr < 96 && sr >= 0 && sr < 3)
                    v = in[base + (long)(ci0 + k) * cStride + lr * lStride + sr * sStride];
                sI[(k * 34 + l) * 5 + s] = v;
            }
        }
        __syncthreads();

        // ---- compute ----
        #pragma unroll 2
        for (int kk = 0; kk < 16; kk++) {
            float rin[4][5];
            #pragma unroll
            for (int li = 0; li < 4; li++)
                #pragma unroll
                for (int s = 0; s < 5; s++)
                    rin[li][s] = sI[(kk * 34 + lp + li) * 5 + s];
            #pragma unroll
            for (int t = 0; t < 9; t++) {
                const int dl = t / 3, ds = t % 3;
                const float a0 = sW[(kk * 9 + t) * 65 + ty4 + 0];
                const float a1 = sW[(kk * 9 + t) * 65 + ty4 + 1];
                const float a2 = sW[(kk * 9 + t) * 65 + ty4 + 2];
                const float a3 = sW[(kk * 9 + t) * 65 + ty4 + 3];
                #pragma unroll
                for (int li = 0; li < 2; li++)
                    #pragma unroll
                    for (int s = 0; s < 3; s++) {
                        const float iv = rin[li + dl][s + ds];
                        acc[0][li][s] += a0 * iv;
                        acc[1][li][s] += a1 * iv;
                        acc[2][li][s] += a2 * iv;
                        acc[3][li][s] += a3 * iv;
                    }
            }
        }
        __syncthreads();
    }

    // ---- bias + ReLU + store ----
    #pragma unroll
    for (int m = 0; m < 4; m++) {
        const int co = co0 + ty4 + m;
        const float bv = bias[co];
        #pragma unroll
        for (int li = 0; li < 2; li++) {
            const int l = l0 + lp + li;
            #pragma unroll
            for (int s = 0; s < 3; s++) {
                float v = acc[m][li][s] + bv;
                out[base + (long)co * cStride + l * lStride + s * sStride] =
                    fmaxf(v, 0.f);
            }
        }
    }
}

// ---------------------------------------------------------------------------
// kernel_launch
// Inputs (metadata order): x, w_channel, w_w, w_H, w_lr, b_lr, w_du, b_du
// ---------------------------------------------------------------------------
extern "C" void kernel_launch(void* const* d_in, const int* in_sizes, int n_in,
                              void* d_out, int out_size) {
    const float* x         = (const float*)d_in[0];
    const float* w_channel = (const float*)d_in[1];
    const float* w_w       = (const float*)d_in[2];
    const float* w_H       = (const float*)d_in[3];
    const float* w_lr      = (const float*)d_in[4];
    const float* b_lr      = (const float*)d_in[5];
    const float* w_du      = (const float*)d_in[6];
    const float* b_du      = (const float*)d_in[7];
    float* out = (float*)d_out;

    float *y1, *y2, *xp, *t1, *t2, *y3, *xh, *t3;
    cudaGetSymbolAddress((void**)&y1, g_y1);
    cudaGetSymbolAddress((void**)&y2, g_y2);
    cudaGetSymbolAddress((void**)&xp, g_xp);
    cudaGetSymbolAddress((void**)&t1, g_t1);
    cudaGetSymbolAddress((void**)&t2, g_t2);
    cudaGetSymbolAddress((void**)&y3, g_y3);
    cudaGetSymbolAddress((void**)&xh, g_xh);
    cudaGetSymbolAddress((void**)&t3, g_t3);

    const dim3 blk(256);

    // Stage 1: y1 = w_channel @ x    [512,2048]@[2048,2304] per batch
    gemm128<<<dim3(18, 4, 4), blk>>>(w_channel, x, y1, 512, 2304, 2048,
                                     2048L * 2304, 512L * 2304);
    // Stage 2: y2 = w_w @ y1         [1024,512]@[512,2304]
    gemm128<<<dim3(18, 8, 4), blk>>>(w_w, y1, y2, 1024, 2304, 512,
                                     512L * 2304, 1024L * 2304);
    // Stage 3: pixel-shuffle along H: [4,1024,48,48] -> [4,512,96,48]
    shuffleH_kernel<<<(4 * 512 * 96 * 48 + 255) / 256, blk>>>(y2, xp,
                                                              4 * 512 * 96 * 48);
    // Stage 4: convLR x2 (3-col chunks, 16 chunks of width 3)
    conv3x3_chunk<<<dim3(8, 3, 4 * 16), blk>>>(xp, w_lr, b_lr, t1,
        16, 96 * 48, 48, 1, 512 * 96 * 48, 3, 1, 1);
    conv3x3_chunk<<<dim3(8, 3, 4 * 16), blk>>>(t1, w_lr, b_lr, t2,
        16, 96 * 48, 48, 1, 512 * 96 * 48, 3, 1, 1);
    // Stage 5: y3 = w_H @ t2         [1024,512]@[512,4608]
    gemm128<<<dim3(36, 8, 4), blk>>>(w_H, t2, y3, 1024, 4608, 512,
                                     512L * 4608, 1024L * 4608);
    // Stage 6: pixel-shuffle along W: [4,1024,96,48] -> [4,512,96,96]
    shuffleW_kernel<<<(4 * 512 * 96 * 96 + 255) / 256, blk>>>(y3, xh,
                                                              4 * 512 * 96 * 96);
    // Stage 7: convDU x2 (3-row chunks, 32 chunks of height 3)
    conv3x3_chunk<<<dim3(8, 3, 4 * 32), blk>>>(xh, w_du, b_du, t3,
        32, 96 * 96, 1, 96, 512 * 96 * 96, 1, 3, 0);
    conv3x3_chunk<<<dim3(8, 3, 4 * 32), blk>>>(t3, w_du, b_du, out,
        32, 96 * 96, 1, 96, 512 * 96 * 96, 1, 3, 0);
}

// round 2
// speedup vs baseline: 1.0009x; 1.0009x over previous
#include <cuda_runtime.h>

// ---------------------------------------------------------------------------
// SSRupsampling: x[4,2048,48,48] ->
//   1x1(w_channel) -> 1x1(w_w) -> pixelshuffle-H -> (3x3 conv+ReLU)x2 on 3-col
//   chunks -> 1x1(w_H) -> pixelshuffle-W -> (3x3 conv+ReLU)x2 on 3-row chunks
// Output [4,512,96,96] fp32.
// All fp32 FFMA this round (accuracy-safe baseline).
// ---------------------------------------------------------------------------

// Scratch buffers (static device globals: allocation-free).
__device__ float g_y1[4 * 512 * 2304];        // after w_channel   (18.9 MB)
__device__ float g_y2[4 * 1024 * 2304];       // after w_w         (37.7 MB)
__device__ float g_xp[4 * 512 * 96 * 48];     // after H-shuffle   (37.7 MB)
__device__ float g_t1[4 * 512 * 96 * 48];     // convLR pass 1
__device__ float g_t2[4 * 512 * 96 * 48];     // convLR pass 2
__device__ float g_y3[4 * 1024 * 96 * 48];    // after w_H         (75.5 MB)
__device__ float g_xh[4 * 512 * 96 * 96];     // after W-shuffle   (75.5 MB)
__device__ float g_t3[4 * 512 * 96 * 96];     // convDU pass 1

// ---------------------------------------------------------------------------
// Batched GEMM: C[z] = A @ B[z].  A: [M,K] row-major (shared across batch),
// B[z]: [K,N] row-major, C[z]: [M,N] row-major.
// Tile 128x128, BK=8, 256 threads, 8x8 per-thread register tile.
// Requires M%128==0, N%128==0, K%8==0 (true for all three call sites).
// ---------------------------------------------------------------------------
__global__ __launch_bounds__(256)
void gemm128(const float* __restrict__ A, const float* __restrict__ B,
             float* __restrict__ C, int M, int N, int K,
             long strideB, long strideC) {
    __shared__ float sA[8][128];   // sA[k][m]
    __shared__ float sB[8][128];   // sB[k][n]

    const int tid = threadIdx.x;
    const int n0 = blockIdx.x * 128;
    const int m0 = blockIdx.y * 128;
    const float* Bb = B + (long)blockIdx.z * strideB;
    float* Cb = C + (long)blockIdx.z * strideC;

    const int tx = tid & 15;          // 16 n-groups of 8
    const int ty = tid >> 4;          // 16 m-groups of 8

    // A loader: row = tid/2 (0..127), kvec = (tid&1)*4
    const int arow = tid >> 1;
    const int akv  = (tid & 1) * 4;
    // B loader: krow = tid/32 (0..7), nvec = (tid&31)*4
    const int brow = tid >> 5;
    const int bnv  = (tid & 31) * 4;

    float acc[8][8];
    #pragma unroll
    for (int i = 0; i < 8; i++)
        #pragma unroll
        for (int j = 0; j < 8; j++) acc[i][j] = 0.f;

    for (int k0 = 0; k0 < K; k0 += 8) {
        float4 av = *(const float4*)&A[(long)(m0 + arow) * K + k0 + akv];
        sA[akv + 0][arow] = av.x;
        sA[akv + 1][arow] = av.y;
        sA[akv + 2][arow] = av.z;
        sA[akv + 3][arow] = av.w;
        *(float4*)&sB[brow][bnv] =
            *(const float4*)&Bb[(long)(k0 + brow) * N + n0 + bnv];
        __syncthreads();

        #pragma unroll
        for (int kk = 0; kk < 8; kk++) {
            float a[8], b[8];
            *(float4*)&a[0] = *(const float4*)&sA[kk][ty * 8];
            *(float4*)&a[4] = *(const float4*)&sA[kk][ty * 8 + 4];
            *(float4*)&b[0] = *(const float4*)&sB[kk][tx * 8];
            *(float4*)&b[4] = *(const float4*)&sB[kk][tx * 8 + 4];
            #pragma unroll
            for (int i = 0; i < 8; i++)
                #pragma unroll
                for (int j = 0; j < 8; j++)
                    acc[i][j] += a[i] * b[j];
        }
        __syncthreads();
    }

    #pragma unroll
    for (int i = 0; i < 8; i++) {
        float* crow = &Cb[(long)(m0 + ty * 8 + i) * N + n0 + tx * 8];
        *(float4*)&crow[0] = make_float4(acc[i][0], acc[i][1], acc[i][2], acc[i][3]);
        *(float4*)&crow[4] = make_float4(acc[i][4], acc[i][5], acc[i][6], acc[i][7]);
    }
}

// ---------------------------------------------------------------------------
// Pixel shuffles (cheap permutes).
// ---------------------------------------------------------------------------
__global__ void shuffleH_kernel(const float* __restrict__ src,
                                float* __restrict__ dst, int total) {
    int i = blockIdx.x * blockDim.x + threadIdx.x;
    if (i >= total) return;
    int w  = i % 48;
    int h2 = (i / 48) % 96;
    int c  = (i / (48 * 96)) % 512;
    int n  = i / (48 * 96 * 512);
    // xp[n,c,h2,w] = y2[n, c + 512*(h2&1), h2>>1, w]
    dst[i] = src[(((long)n * 1024 + c + 512 * (h2 & 1)) * 48 + (h2 >> 1)) * 48 + w];
}

__global__ void shuffleW_kernel(const float* __restrict__ src,
                                float* __restrict__ dst, int total) {
    int i = blockIdx.x * blockDim.x + threadIdx.x;
    if (i >= total) return;
    int w2 = i % 96;
    int h  = (i / 96) % 96;
    int c  = (i / (96 * 96)) % 512;
    int n  = i / (96 * 96 * 512);
    // xh[n,c,h,w2] = y3[n, c + 512*(w2&1), h, w2>>1]
    dst[i] = src[(((long)n * 1024 + c + 512 * (w2 & 1)) * 96 + h) * 48 + (w2 >> 1)];
}

// ---------------------------------------------------------------------------
// Generic chunked 3x3 conv + bias + ReLU, implicit GEMM.
// Logical image per (n, chunk): [C=512][L=96][S=3] with zero padding on L and S.
// Element (n, c, l, s) at: n*nStride + c*cStride + l*lStride + (chunk*3+s)*sStride
// Weight tap (dl, ds): w[co*4608 + ci*9 + dl*tapL + ds*tapS]
//   convLR: long=H (kh), short=W (kw) -> tapL=3, tapS=1, sInner=1 (s is stride-1)
//   convDU: long=W (kw), short=H (kh) -> tapL=1, tapS=3, sInner=0 (l is stride-1)
// Block: 64 couts x (32 L-rows x 3 S) = 64x96 outputs, 256 threads,
// each thread: 4 couts x 2 rows x 3 cols = 24 accumulators. BK = 16.
// ---------------------------------------------------------------------------
__global__ __launch_bounds__(256, 2)
void conv3x3_chunk(const float* __restrict__ in, const float* __restrict__ w,
                   const float* __restrict__ bias, float* __restrict__ out,
                   int nChunks, int cStride, int lStride, int sStride,
                   int nStride, int tapL, int tapS, int sInner) {
    // sW[k][tap][co], padded co-stride 65 for conflict-free stores/loads
    __shared__ float sW[16 * 9 * 65];       // 37,440 B
    __shared__ float sI[16 * 34 * 5];       // 10,880 B  (l halo 34, s padded 5)

    const int tid = threadIdx.x;
    const int co0 = blockIdx.x * 64;
    const int l0  = blockIdx.y * 32;
    const int z   = blockIdx.z;
    const int n     = z / nChunks;
    const int chunk = z % nChunks;
    const long base = (long)n * nStride + (long)chunk * 3 * sStride;

    const int tx = tid & 15;         // 16 L-groups of 2 rows
    const int ty = tid >> 4;         // 16 cout-groups of 4
    const int lp = tx * 2;
    const int ty4 = ty * 4;

    float acc[4][2][3];
    #pragma unroll
    for (int m = 0; m < 4; m++)
        #pragma unroll
        for (int li = 0; li < 2; li++)
            #pragma unroll
            for (int s = 0; s < 3; s++) acc[m][li][s] = 0.f;

    for (int ci0 = 0; ci0 < 512; ci0 += 16) {
        // ---- load weights: 16 ci x 9 taps x 64 co = 9216 values ----
        #pragma unroll
        for (int it = 0; it < 36; it++) {
            int i = tid + it * 256;
            int co  = i / 144;
            int rem = i % 144;          // rem = k*9 + t (consecutive per thread)
            int k = rem / 9;
            int t = rem % 9;
            int dl = t / 3, ds = t % 3;
            sW[rem * 65 + co] =
                w[(long)(co0 + co) * 4608 + (ci0 + k) * 9 + dl * tapL + ds * tapS];
        }
        // ---- load input tile: 16 ci x 34 l x 5 s (zero halo) = 2720 ----
        #pragma unroll
        for (int it = 0; it < 11; it++) {
            int j = tid + it * 256;
            if (j < 2720) {
                int k = j / 170;
                int r = j % 170;
                int l, s;
                if (sInner) { l = r / 5; s = r % 5; }      // LR: s is gmem-contig
                else        { s = r / 34; l = r % 34; }    // DU: l is gmem-contig
                int lr = l0 - 1 + l;
                int sr = s - 1;
                float v = 0.f;
                if (lr >= 0 && lr < 96 && sr >= 0 && sr < 3)
                    v = in[base + (long)(ci0 + k) * cStride + lr * lStride + sr * sStride];
                sI[(k * 34 + l) * 5 + s] = v;
            }
        }
        __syncthreads();

        // ---- compute ----
        #pragma unroll 2
        for (int kk = 0; kk < 16; kk++) {
            float rin[4][5];
            #pragma unroll
            for (int li = 0; li < 4; li++)
                #pragma unroll
                for (int s = 0; s < 5; s++)
                    rin[li][s] = sI[(kk * 34 + lp + li) * 5 + s];
            #pragma unroll
            for (int t = 0; t < 9; t++) {
                const int dl = t / 3, ds = t % 3;
                const float a0 = sW[(kk * 9 + t) * 65 + ty4 + 0];
                const float a1 = sW[(kk * 9 + t) * 65 + ty4 + 1];
                const float a2 = sW[(kk * 9 + t) * 65 + ty4 + 2];
                const float a3 = sW[(kk * 9 + t) * 65 + ty4 + 3];
                #pragma unroll
                for (int li = 0; li < 2; li++)
                    #pragma unroll
                    for (int s = 0; s < 3; s++) {
                        const float iv = rin[li + dl][s + ds];
                        acc[0][li][s] += a0 * iv;
                        acc[1][li][s] += a1 * iv;
                        acc[2][li][s] += a2 * iv;
                        acc[3][li][s] += a3 * iv;
                    }
            }
        }
        __syncthreads();
    }

    // ---- bias + ReLU + store ----
    #pragma unroll
    for (int m = 0; m < 4; m++) {
        const int co = co0 + ty4 + m;
        const float bv = bias[co];
        #pragma unroll
        for (int li = 0; li < 2; li++) {
            const int l = l0 + lp + li;
            #pragma unroll
            for (int s = 0; s < 3; s++) {
                float v = acc[m][li][s] + bv;
                out[base + (long)co * cStride + l * lStride + s * sStride] =
                    fmaxf(v, 0.f);
            }
        }
    }
}

// ---------------------------------------------------------------------------
// kernel_launch
// Inputs (metadata order): x, w_channel, w_w, w_H, w_lr, b_lr, w_du, b_du
// ---------------------------------------------------------------------------
extern "C" void kernel_launch(void* const* d_in, const int* in_sizes, int n_in,
                              void* d_out, int out_size) {
    const float* x         = (const float*)d_in[0];
    const float* w_channel = (const float*)d_in[1];
    const float* w_w       = (const float*)d_in[2];
    const float* w_H       = (const float*)d_in[3];
    const float* w_lr      = (const float*)d_in[4];
    const float* b_lr      = (const float*)d_in[5];
    const float* w_du      = (const float*)d_in[6];
    const float* b_du      = (const float*)d_in[7];
    float* out = (float*)d_out;

    float *y1, *y2, *xp, *t1, *t2, *y3, *xh, *t3;
    cudaGetSymbolAddress((void**)&y1, g_y1);
    cudaGetSymbolAddress((void**)&y2, g_y2);
    cudaGetSymbolAddress((void**)&xp, g_xp);
    cudaGetSymbolAddress((void**)&t1, g_t1);
    cudaGetSymbolAddress((void**)&t2, g_t2);
    cudaGetSymbolAddress((void**)&y3, g_y3);
    cudaGetSymbolAddress((void**)&xh, g_xh);
    cudaGetSymbolAddress((void**)&t3, g_t3);

    const dim3 blk(256);

    // Stage 1: y1 = w_channel @ x    [512,2048]@[2048,2304] per batch
    gemm128<<<dim3(18, 4, 4), blk>>>(w_channel, x, y1, 512, 2304, 2048,
                                     2048L * 2304, 512L * 2304);
    // Stage 2: y2 = w_w @ y1         [1024,512]@[512,2304]
    gemm128<<<dim3(18, 8, 4), blk>>>(w_w, y1, y2, 1024, 2304, 512,
                                     512L * 2304, 1024L * 2304);
    // Stage 3: pixel-shuffle along H: [4,1024,48,48] -> [4,512,96,48]
    shuffleH_kernel<<<(4 * 512 * 96 * 48 + 255) / 256, blk>>>(y2, xp,
                                                              4 * 512 * 96 * 48);
    // Stage 4: convLR x2 (3-col chunks, 16 chunks of width 3)
    conv3x3_chunk<<<dim3(8, 3, 4 * 16), blk>>>(xp, w_lr, b_lr, t1,
        16, 96 * 48, 48, 1, 512 * 96 * 48, 3, 1, 1);
    conv3x3_chunk<<<dim3(8, 3, 4 * 16), blk>>>(t1, w_lr, b_lr, t2,
        16, 96 * 48, 48, 1, 512 * 96 * 48, 3, 1, 1);
    // Stage 5: y3 = w_H @ t2         [1024,512]@[512,4608]
    gemm128<<<dim3(36, 8, 4), blk>>>(w_H, t2, y3, 1024, 4608, 512,
                                     512L * 4608, 1024L * 4608);
    // Stage 6: pixel-shuffle along W: [4,1024,96,48] -> [4,512,96,96]
    shuffleW_kernel<<<(4 * 512 * 96 * 96 + 255) / 256, blk>>>(y3, xh,
                                                              4 * 512 * 96 * 96);
    // Stage 7: convDU x2 (3-row chunks, 32 chunks of height 3)
    conv3x3_chunk<<<dim3(8, 3, 4 * 32), blk>>>(xh, w_du, b_du, t3,
        32, 96 * 96, 1, 96, 512 * 96 * 96, 1, 3, 0);
    conv3x3_chunk<<<dim3(8, 3, 4 * 32), blk>>>(t3, w_du, b_du, out,
        32, 96 * 96, 1, 96, 512 * 96 * 96, 1, 3, 0);
}